// round 17
// baseline (speedup 1.0000x reference)
#include <cuda_runtime.h>
#include <cstdint>
#include <math.h>

#define NPTS 3072
#define NOUT 16
#define NBLK 384
#define NTHR 512
#define TOTTHR (NBLK * NTHR)        // 196608 = 64 * 3072
#define ISTRIDE (TOTTHR / NPTS)     // 64
#define NITER (NPTS / ISTRIDE)      // 48

// Persistent single-wave dense kernel: 384 resident CTAs, each thread owns a
// fixed j column (j-coords register-resident for all 48 iterations) and walks
// i in strides of 64. Two 256-bit streaming stores per pair — the config
// measured at the HBM write floor (~7.4 TB/s) in R14-R16.
__global__ __launch_bounds__(NTHR) void dense_v8_persist_kernel(
    const float* __restrict__ coord,
    const float* __restrict__ sig,
    float* __restrict__ out)
{
    __shared__ float s_inv[NOUT];   // 1/(2*sigma_c^2), reference rounding
    __shared__ float s_qden, s_lo, s_hi;

    if (threadIdx.x < NOUT) {
        float s = sig[threadIdx.x];
        s_inv[threadIdx.x] = __fdiv_rn(1.0f, __fmul_rn(__fmul_rn(2.0f, s), s));
    }
    if (threadIdx.x == 0) {
        float sm = sig[NOUT - 1];
        float qd = __fmul_rn(__fmul_rn(2.0f, sm), sm);
        s_qden = qd;
        s_lo = 0.105300f * qd;   // conservative fast-keep bound
        s_hi = 0.105420f * qd;   // conservative fast-drop bound
    }
    __syncthreads();

    const int g  = blockIdx.x * NTHR + threadIdx.x;
    const int j  = g % NPTS;          // constant across iterations
    const int i0 = g / NPTS;          // 0..63

    const float xj = __ldg(coord + 3 * j + 0);
    const float yj = __ldg(coord + 3 * j + 1);
    const float zj = __ldg(coord + 3 * j + 2);
    const float sqj = __fadd_rn(__fadd_rn(__fmul_rn(xj, xj), __fmul_rn(yj, yj)),
                                __fmul_rn(zj, zj));

    const float lo = s_lo, hi = s_hi, qden = s_qden;
    float inv[NOUT];
#pragma unroll
    for (int c = 0; c < NOUT; c++) inv[c] = s_inv[c];

    float* base = out + ((size_t)i0 * NPTS + j) * NOUT;   // 64B-aligned
    const size_t step = (size_t)ISTRIDE * NPTS * NOUT;    // advance 64 i-rows

#pragma unroll 2
    for (int n = 0; n < NITER; n++) {
        const int i = i0 + n * ISTRIDE;

        const float xi = __ldg(coord + 3 * i + 0);
        const float yi = __ldg(coord + 3 * i + 1);
        const float zi = __ldg(coord + 3 * i + 2);

        // sq = (x*x + y*y) + z*z, no fma contraction (matches reference)
        const float sqi = __fadd_rn(__fadd_rn(__fmul_rn(xi, xi), __fmul_rn(yi, yi)),
                                    __fmul_rn(zi, zi));
        // dot via ascending-k fma chain (matches host fma path)
        const float dot = __fmaf_rn(zi, zj, __fmaf_rn(yi, yj, __fmul_rn(xi, xj)));

        float d2 = __fsub_rn(__fadd_rn(sqi, sqj), __fmul_rn(2.0f, dot));
        d2 = fmaxf(d2, 0.0f);

        // keep = (exp(-d2/(2*smax^2)) >= 0.9) && d2 > 0 && i != j
        bool keep;
        if (d2 <= lo) {
            keep = (d2 > 0.0f) && (i != j);
        } else if (d2 >= hi) {
            keep = false;
        } else {
            // boundary band: reproduce reference predicate exactly
            const float q = __fdiv_rn(d2, qden);
            if (q <= 0.105340f)       keep = true;
            else if (q >= 0.105380f)  keep = false;
            else                      keep = ((float)exp(-(double)q) >= 0.9f);
            keep = keep && (d2 > 0.0f) && (i != j);
        }

        float v[NOUT];
#pragma unroll
        for (int c = 0; c < NOUT; c++) v[c] = 0.0f;
        if (keep) {
#pragma unroll
            for (int c = 0; c < NOUT; c++)
                v[c] = __expf(-__fmul_rn(d2, inv[c]));
        }

        asm volatile(
            "st.global.cs.v8.f32 [%0], {%1,%2,%3,%4,%5,%6,%7,%8};"
            :: "l"(base),
               "f"(v[0]), "f"(v[1]), "f"(v[2]), "f"(v[3]),
               "f"(v[4]), "f"(v[5]), "f"(v[6]), "f"(v[7])
            : "memory");
        asm volatile(
            "st.global.cs.v8.f32 [%0], {%1,%2,%3,%4,%5,%6,%7,%8};"
            :: "l"(base + 8),
               "f"(v[8]),  "f"(v[9]),  "f"(v[10]), "f"(v[11]),
               "f"(v[12]), "f"(v[13]), "f"(v[14]), "f"(v[15])
            : "memory");

        base += step;
    }
}

extern "C" void kernel_launch(void* const* d_in, const int* in_sizes, int n_in,
                              void* d_out, int out_size)
{
    const float* coord = (const float*)d_in[0];   // [3072, 3] fp32
    const float* sig   = (const float*)d_in[1];   // [16] fp32
    float* out = (float*)d_out;                   // [1, 3072, 3072, 16] fp32

    dense_v8_persist_kernel<<<NBLK, NTHR>>>(coord, sig, out);
}